// round 10
// baseline (speedup 1.0000x reference)
#include <cuda_runtime.h>
#include <cuda_bf16.h>
#include <math.h>

#define BATCH 2
#define NPTS  8192
#define CH    128
#define KNN   8
#define MTOT  (BATCH * NPTS)

// ---------------- scratch (no allocations allowed) ----------------
__device__ float g_q[MTOT * CH];
__device__ float g_k[MTOT * CH];
__device__ float g_v[MTOT * CH];
__device__ float g_agg[MTOT * CH];     // attention output, fp32
__device__ int   g_idx[MTOT * KNN];

// ---------------- fp32 -> (hi,lo) bf16 split helpers ----------------
__device__ __forceinline__ void split_bf16(float x, unsigned short& h, unsigned short& l) {
    __nv_bfloat16 hb = __float2bfloat16(x);
    float hf = __bfloat162float(hb);
    __nv_bfloat16 lb = __float2bfloat16(x - hf);
    h = __bfloat16_as_ushort(hb);
    l = __bfloat16_as_ushort(lb);
}
__device__ __forceinline__ unsigned pack_hilo(float x) {   // X-pattern word (hi,lo)
    unsigned short h, l; split_bf16(x, h, l);
    return ((unsigned)l << 16) | (unsigned)h;
}
__device__ __forceinline__ void pack_w(float x, unsigned& p0, unsigned& p1) { // (hi,hi),(lo,lo)
    unsigned short h, l; split_bf16(x, h, l);
    p0 = ((unsigned)h << 16) | h;
    p1 = ((unsigned)l << 16) | l;
}

// ---------------- tensor-core GEMM:  Y = X @ W^T via bf16 split-K ----------------
// 64x128 CTA tile, 256 threads = 8 warps (2x4), warp tile 32x32, mma.m16n8k16.
// X fp32 split inline to (hi,lo,hi,lo); W fp32 split inline to (hi,hi,lo,lo).
// smem rows padded to 144B -> conflict-free LDS.32 fragment loads.
__device__ __forceinline__ void mma_gemm_tile(const float* __restrict__ X,
                                              const float* __restrict__ Wf,
                                              float* __restrict__ Y, int m0)
{
    __shared__ __align__(16) unsigned char xs[64 * 144];
    __shared__ __align__(16) unsigned char ws[128 * 144];
    const int tid  = threadIdx.x;
    const int lane = tid & 31;
    const int warp = tid >> 5;
    const int wm   = warp >> 2;       // 0..1 -> rows wm*32
    const int wn   = warp & 3;        // 0..3 -> cols wn*32
    const int g    = lane >> 2;       // 0..7
    const int c4   = lane & 3;        // 0..3

    float acc[2][4][4];
#pragma unroll
    for (int i = 0; i < 2; i++)
#pragma unroll
        for (int t = 0; t < 4; t++)
#pragma unroll
            for (int r = 0; r < 4; r++) acc[i][t][r] = 0.f;

    for (int kc = 0; kc < 8; kc++) {        // K' = 512 in chunks of 64
        __syncthreads();
        // stage X: 64 rows x 8 uint4 = 512 slots, 2 per thread
#pragma unroll
        for (int i = 0; i < 2; i++) {
            int s  = tid + i * 256;
            int r  = s >> 3;
            int f4 = s & 7;
            float2 xv = *(const float2*)(X + (size_t)(m0 + r) * CH + kc * 16 + f4 * 2);
            unsigned p0 = pack_hilo(xv.x), p1 = pack_hilo(xv.y);
            *(uint4*)(xs + r * 144 + f4 * 16) = make_uint4(p0, p0, p1, p1);
        }
        // stage W: 128 rows x 8 uint4 = 1024 slots, 4 per thread
#pragma unroll
        for (int i = 0; i < 4; i++) {
            int s  = tid + i * 256;
            int r  = s >> 3;
            int f4 = s & 7;
            float2 wv = *(const float2*)(Wf + (size_t)r * CH + kc * 16 + f4 * 2);
            unsigned a0, a1, b0, b1;
            pack_w(wv.x, a0, a1);
            pack_w(wv.y, b0, b1);
            *(uint4*)(ws + r * 144 + f4 * 16) = make_uint4(a0, a1, b0, b1);
        }
        __syncthreads();
#pragma unroll
        for (int ks = 0; ks < 4; ks++) {    // 4 x k16 steps
            unsigned a[2][4], b[4][2];
#pragma unroll
            for (int i = 0; i < 2; i++)
#pragma unroll
                for (int j = 0; j < 4; j++) {
                    int row = wm * 32 + i * 16 + g + 8 * (j & 1);
                    int off = ks * 32 + (j >> 1) * 16 + c4 * 4;
                    a[i][j] = *(const unsigned*)(xs + row * 144 + off);
                }
#pragma unroll
            for (int t = 0; t < 4; t++)
#pragma unroll
                for (int r = 0; r < 2; r++) {
                    int n   = wn * 32 + t * 8 + g;
                    int off = ks * 32 + r * 16 + c4 * 4;
                    b[t][r] = *(const unsigned*)(ws + n * 144 + off);
                }
#pragma unroll
            for (int i = 0; i < 2; i++)
#pragma unroll
                for (int t = 0; t < 4; t++)
                    asm volatile(
                        "mma.sync.aligned.m16n8k16.row.col.f32.bf16.bf16.f32 "
                        "{%0,%1,%2,%3}, {%4,%5,%6,%7}, {%8,%9}, {%0,%1,%2,%3};"
                        : "+f"(acc[i][t][0]), "+f"(acc[i][t][1]),
                          "+f"(acc[i][t][2]), "+f"(acc[i][t][3])
                        : "r"(a[i][0]), "r"(a[i][1]), "r"(a[i][2]), "r"(a[i][3]),
                          "r"(b[t][0]), "r"(b[t][1]));
        }
    }
#pragma unroll
    for (int i = 0; i < 2; i++)
#pragma unroll
        for (int t = 0; t < 4; t++) {
            int row = m0 + wm * 32 + i * 16 + g;
            int col = wn * 32 + t * 8 + 2 * c4;
            *(float2*)(Y + (size_t)row * CH + col)       = make_float2(acc[i][t][0], acc[i][t][1]);
            *(float2*)(Y + (size_t)(row + 8) * CH + col) = make_float2(acc[i][t][2], acc[i][t][3]);
        }
}

__global__ __launch_bounds__(256) void qkv_mma_kernel(const float* __restrict__ feats,
                                                      const float* __restrict__ Wq,
                                                      const float* __restrict__ Wk,
                                                      const float* __restrict__ Wv)
{
    int w = blockIdx.y;
    const float* W = (w == 0) ? Wq : (w == 1) ? Wk : Wv;
    float* Y = (w == 0) ? g_q : (w == 1) ? g_k : g_v;
    mma_gemm_tile(feats, W, Y, blockIdx.x * 64);
}

__global__ __launch_bounds__(256) void out_mma_kernel(const float* __restrict__ Wo,
                                                      float* __restrict__ out)
{
    mma_gemm_tile(g_agg, Wo, out, blockIdx.x * 64);
}

// ---------------- KNN: warp top-8; scalar fast path + lane-min insert ----------
// e-space ordering: e = csq - 2*dot (query-constant shift of d2; same top-k set).
// Fast path: 4 candidates/lane (float4 LDS from SoA), 3 FMA each, one __any
// per 128-candidate group per query. On fire: each lane submits only its
// current minimum; ballot-walk inserts; consumed slots -> +inf; re-ballot.
#define QW  4
#define CCH 2048

__global__ __launch_bounds__(256, 3) void knn_kernel(const float* __restrict__ coords,
                                                     int* __restrict__ out_idx)
{
    __shared__ float sx[CCH], sy[CCH], sz[CCH], ss[CCH];
    const unsigned full = 0xffffffffu;
    const int b     = blockIdx.y;
    const int warp  = threadIdx.x >> 5;
    const int lane  = threadIdx.x & 31;
    const int qbase = blockIdx.x * (8 * QW) + warp * QW;
    const float* cb = coords + (size_t)b * NPTS * 3;

    float m2x[QW], m2y[QW], m2z[QW];
#pragma unroll
    for (int u = 0; u < QW; u++) {
        m2x[u] = -2.f * cb[(qbase + u) * 3 + 0];
        m2y[u] = -2.f * cb[(qbase + u) * 3 + 1];
        m2z[u] = -2.f * cb[(qbase + u) * 3 + 2];
    }

    float val[QW], thr[QW];
    int idx[QW];
#pragma unroll
    for (int u = 0; u < QW; u++) { val[u] = 3.0e38f; thr[u] = 3.0e38f; idx[u] = -1; }

    for (int c0 = 0; c0 < NPTS; c0 += CCH) {
        __syncthreads();
        for (int t = threadIdx.x; t < CCH; t += 256) {
            float x = cb[(c0 + t) * 3 + 0];
            float y = cb[(c0 + t) * 3 + 1];
            float z = cb[(c0 + t) * 3 + 2];
            sx[t] = x; sy[t] = y; sz[t] = z;
            ss[t] = fmaf(z, z, fmaf(y, y, x * x));
        }
        __syncthreads();

        for (int j0 = 0; j0 < CCH; j0 += 128) {
            int base = j0 + lane * 4;
            float4 cx = *(const float4*)&sx[base];
            float4 cy = *(const float4*)&sy[base];
            float4 cz = *(const float4*)&sz[base];
            float4 cs = *(const float4*)&ss[base];
            int jb = c0 + j0;                        // warp-uniform
#pragma unroll
            for (int u = 0; u < QW; u++) {
                float e0 = fmaf(m2z[u], cz.x, fmaf(m2y[u], cy.x, fmaf(m2x[u], cx.x, cs.x)));
                float e1 = fmaf(m2z[u], cz.y, fmaf(m2y[u], cy.y, fmaf(m2x[u], cx.y, cs.y)));
                float e2 = fmaf(m2z[u], cz.z, fmaf(m2y[u], cy.z, fmaf(m2x[u], cx.z, cs.z)));
                float e3 = fmaf(m2z[u], cz.w, fmaf(m2y[u], cy.w, fmaf(m2x[u], cx.w, cs.w)));
                float lm0 = fminf(fminf(e0, e1), fminf(e2, e3));
                if (!__any_sync(full, lm0 < thr[u])) continue;

                // slow path: lane submits its current minimum; insert; repeat
                float a0 = e0, a1 = e1, a2 = e2, a3 = e3;
                for (;;) {
                    float lm = a0; int li = 0;
                    if (a1 < lm) { lm = a1; li = 1; }
                    if (a2 < lm) { lm = a2; li = 2; }
                    if (a3 < lm) { lm = a3; li = 3; }
                    unsigned mb = __ballot_sync(full, lm < thr[u]);
                    if (!mb) break;
                    unsigned m = mb;
                    while (m) {
                        int src = __ffs(m) - 1;
                        m &= m - 1;
                        float dn = __shfl_sync(full, lm, src);
                        if (dn < thr[u]) {           // warp-uniform
                            int sl = __shfl_sync(full, li, src);
                            int in = jb + (src << 2) + sl;
                            float pv = __shfl_up_sync(full, val[u], 1);
                            int   pi = __shfl_up_sync(full, idx[u], 1);
                            unsigned le = __ballot_sync(full, val[u] <= dn);
                            int pos = __popc(le & 0xff);
                            if (lane == pos)                 { val[u] = dn; idx[u] = in; }
                            else if (lane > pos && lane < 8) { val[u] = pv; idx[u] = pi; }
                            thr[u] = __shfl_sync(full, val[u], 7);
                        }
                    }
                    if ((mb >> lane) & 1) {          // consume submitted minimum
                        if (li == 0) a0 = 3.0e38f;
                        else if (li == 1) a1 = 3.0e38f;
                        else if (li == 2) a2 = 3.0e38f;
                        else a3 = 3.0e38f;
                    }
                }
            }
        }
    }

    if (lane < KNN) {
#pragma unroll
        for (int u = 0; u < QW; u++)
            out_idx[((size_t)b * NPTS + qbase + u) * KNN + lane] = idx[u];
    }
}

// ---------------- attention over K=8 neighbors (float4, fp32 agg out) ----------
__global__ __launch_bounds__(256) void attn_kernel(const float* __restrict__ coords,
                                                   const float* __restrict__ logg)
{
    const int gq   = blockIdx.x * 8 + (threadIdx.x >> 5);
    const int b    = gq >> 13;
    const int q    = gq & (NPTS - 1);
    const int lane = threadIdx.x & 31;
    const float lg = *logg;
    const float inv_sqrt_c = 0.08838834764831845f;   // 1/sqrt(128)

    float4 qv = *(const float4*)(g_q + (size_t)gq * CH + lane * 4);

    const float* cb = coords + (size_t)b * NPTS * 3;
    const float qx = cb[q * 3 + 0], qy = cb[q * 3 + 1], qz = cb[q * 3 + 2];

    int nb[KNN];
#pragma unroll
    for (int t = 0; t < KNN; t++) nb[t] = g_idx[(size_t)gq * KNN + t];

    float sc[KNN];
#pragma unroll
    for (int t = 0; t < KNN; t++) {
        float4 kv = *(const float4*)(g_k + ((size_t)b * NPTS + nb[t]) * CH + lane * 4);
        float d = qv.x * kv.x;
        d = fmaf(qv.y, kv.y, d);
        d = fmaf(qv.z, kv.z, d);
        d = fmaf(qv.w, kv.w, d);
#pragma unroll
        for (int off = 16; off; off >>= 1) d += __shfl_xor_sync(0xffffffffu, d, off);
        float dx = qx - cb[nb[t] * 3 + 0];
        float dy = qy - cb[nb[t] * 3 + 1];
        float dz = qz - cb[nb[t] * 3 + 2];
        float d2 = fmaf(dz, dz, fmaf(dy, dy, dx * dx));
        float dist = (d2 > 0.f) ? sqrtf(d2) : 0.f;     // _safe_norm
        float gw = expf(lg * dist);
        sc[t] = d * inv_sqrt_c * gw;
    }
    float m = sc[0];
#pragma unroll
    for (int t = 1; t < KNN; t++) m = fmaxf(m, sc[t]);
    float ssum = 0.f;
#pragma unroll
    for (int t = 0; t < KNN; t++) { sc[t] = expf(sc[t] - m); ssum += sc[t]; }
    float inv = 1.f / ssum;

    float4 acc = make_float4(0.f, 0.f, 0.f, 0.f);
#pragma unroll
    for (int t = 0; t < KNN; t++) {
        float4 vv = *(const float4*)(g_v + ((size_t)b * NPTS + nb[t]) * CH + lane * 4);
        float wt = sc[t] * inv;
        acc.x = fmaf(wt, vv.x, acc.x);
        acc.y = fmaf(wt, vv.y, acc.y);
        acc.z = fmaf(wt, vv.z, acc.z);
        acc.w = fmaf(wt, vv.w, acc.w);
    }
    *(float4*)(g_agg + (size_t)gq * CH + lane * 4) = acc;
}

// ---------------- launch ----------------
extern "C" void kernel_launch(void* const* d_in, const int* in_sizes, int n_in,
                              void* d_out, int out_size)
{
    const float* feats  = (const float*)d_in[0];
    const float* coords = (const float*)d_in[1];
    const float* Wq     = (const float*)d_in[2];
    const float* Wk     = (const float*)d_in[3];
    const float* Wv     = (const float*)d_in[4];
    const float* Wo     = (const float*)d_in[5];
    const float* logg   = (const float*)d_in[6];
    float* out = (float*)d_out;

    int* idx_ptr = nullptr;
    cudaGetSymbolAddress((void**)&idx_ptr, g_idx);

    // KNN top-8 per query (32 queries/CTA)
    knn_kernel<<<dim3(NPTS / 32, BATCH), 256>>>(coords, idx_ptr);

    // q,k,v projections on tensor cores (feats + W split inline)
    qkv_mma_kernel<<<dim3(MTOT / 64, 3), 256>>>(feats, Wq, Wk, Wv);

    // neighbor attention -> g_agg (fp32)
    attn_kernel<<<MTOT / 8, 256>>>(coords, logg);

    // output projection (agg + Wo split inline)
    out_mma_kernel<<<MTOT / 64, 256>>>(Wo, out);
}